// round 14
// baseline (speedup 1.0000x reference)
#include <cuda_runtime.h>
#include <cstdint>

typedef unsigned long long u64;

// ---------- packed f32x2 helpers ----------
__device__ __forceinline__ u64 pk2(float lo, float hi) {
    u64 r;
    asm("mov.b64 %0, {%1, %2};" : "=l"(r)
        : "r"(__float_as_uint(lo)), "r"(__float_as_uint(hi)));
    return r;
}
__device__ __forceinline__ void upk(u64 a, float& lo, float& hi) {
    unsigned int l_, h_;
    asm("mov.b64 {%0, %1}, %2;" : "=r"(l_), "=r"(h_) : "l"(a));
    lo = __uint_as_float(l_);
    hi = __uint_as_float(h_);
}
__device__ __forceinline__ u64 dfma(u64 a, u64 b, u64 c) {
    u64 d;
    asm("fma.rn.f32x2 %0, %1, %2, %3;" : "=l"(d) : "l"(a), "l"(b), "l"(c));
    return d;
}
__device__ __forceinline__ u64 dmul(u64 a, u64 b) {
    u64 d;
    asm("mul.rn.f32x2 %0, %1, %2;" : "=l"(d) : "l"(a), "l"(b));
    return d;
}
__device__ __forceinline__ u64 dadd(u64 a, u64 b) {
    u64 d;
    asm("add.rn.f32x2 %0, %1, %2;" : "=l"(d) : "l"(a), "l"(b));
    return d;
}
// 2*relu(x) per half, exact: x + |x| (2x folded into pre-halved W2/W3)
__device__ __forceinline__ u64 drelu2(u64 a) {
    return dadd(a, a & 0x7FFFFFFF7FFFFFFFULL);
}
__device__ __forceinline__ uint32_t smem_u32(const void* p) {
    uint32_t a;
    asm("{ .reg .u64 t; cvta.to.shared.u64 t, %1; cvt.u32.u64 %0, t; }"
        : "=r"(a) : "l"(p));
    return a;
}
// paired weight load (LDS.128, broadcast): two packed u64 weights
__device__ __forceinline__ void ldsw2(uint32_t addr, u64& a, u64& b) {
    asm("ld.shared.v2.u64 {%0, %1}, [%2];" : "=l"(a), "=l"(b) : "r"(addr));
}

// Smem weight layout (u64 packed (v,v)), all pair-reads 16B-aligned:
//  [4j..4j+3]   = W1[j,0], W1[j,1], W1[j,2], b1[j]     j=0..4
//  [20+6j..+5]  = .5*W2[j,0..4], b2[j]                  j=0..4
//  [50..55]     = .5*W3[0..4], b3
//
// One warp = 4 points; 8 lanes per point; each lane loads its own contiguous
// 48B (4 neighbors = 2 packed pairs) and runs ONE dual step. Weights read
// once per thread via broadcast LDS.128 (short threads: no reuse pressure).
__global__ void __launch_bounds__(128)
velvec_kernel(const float* __restrict__ pos, const float* __restrict__ nbr,
              const float* __restrict__ W1, const float* __restrict__ b1,
              const float* __restrict__ W2, const float* __restrict__ b2,
              const float* __restrict__ W3, const float* __restrict__ b3,
              float* __restrict__ out, int N)
{
    __shared__ __align__(16) u64 sw[56];

    int tid = threadIdx.x;
    // prologue: load + pre-scale + pack weights into smem (once per block)
    if (tid < 56) {
        float v;
        if (tid < 20) {
            int jj = tid >> 2, r = tid & 3;
            v = (r < 3) ? __ldg(W1 + 3 * jj + r) : __ldg(b1 + jj);
        } else if (tid < 50) {
            int t = tid - 20, jj = t / 6, r = t - 6 * jj;
            v = (r < 5) ? 0.5f * __ldg(W2 + 5 * jj + r) : __ldg(b2 + jj);
        } else if (tid < 55) {
            v = 0.5f * __ldg(W3 + tid - 50);
        } else {
            v = __ldg(b3);
        }
        unsigned int u = __float_as_uint(v);
        sw[tid] = ((u64)u << 32) | (u64)u;
    }
    __syncthreads();
    uint32_t swb = smem_u32(sw);

    int gw = (blockIdx.x * blockDim.x + tid) >> 5;   // global warp id
    int l = tid & 31;
    int p = l >> 3;            // point within warp's group of 4
    int j = l & 7;             // 48B slice within the point's 384B row
    int n = gw * 4 + p;        // global point index
    int nc = (n < N) ? n : (N - 1);   // clamped for loads; store predicated

    // ---- load this lane's 4 neighbors (3x LDG.128, contiguous 48B) ----
    const float4* bp = reinterpret_cast<const float4*>(
        (const char*)nbr + (size_t)nc * 384 + (size_t)j * 48);
    float4 q0 = __ldg(bp + 0);    // x0 y0 z0 x1
    float4 q1 = __ldg(bp + 1);    // y1 z1 x2 y2
    float4 q2 = __ldg(bp + 2);    // z2 x3 y3 z3

    float px = __ldg(pos + 3 * nc + 0);
    float py = __ldg(pos + 3 * nc + 1);
    float pz = __ldg(pos + 3 * nc + 2);
    u64 npx = pk2(-px, -px), npy = pk2(-py, -py), npz = pk2(-pz, -pz);

    // pair A = neighbors 0,1 of the slice; pair B = neighbors 2,3
    u64 axA = pk2(q0.x, q0.w), ayA = pk2(q0.y, q1.x), azA = pk2(q0.z, q1.y);
    u64 axB = pk2(q1.z, q2.y), ayB = pk2(q1.w, q2.z), azB = pk2(q2.x, q2.w);

    u64 dxA = dadd(axA, npx), dyA = dadd(ayA, npy), dzA = dadd(azA, npz);
    u64 dxB = dadd(axB, npx), dyB = dadd(ayB, npy), dzB = dadd(azB, npz);
    u64 d2A = dfma(dxA, dxA, dfma(dyA, dyA, dmul(dzA, dzA)));
    u64 d2B = dfma(dxB, dxB, dfma(dyB, dyB, dmul(dzB, dzB)));
    float a0, a1, b0, b1v;
    upk(d2A, a0, a1); upk(d2B, b0, b1v);
    float iA0 = rsqrtf(fmaxf(a0, 1e-24f));   // matches v/max(||v||,1e-12)
    float iA1 = rsqrtf(fmaxf(a1, 1e-24f));
    float iB0 = rsqrtf(fmaxf(b0, 1e-24f));
    float iB1 = rsqrtf(fmaxf(b1v, 1e-24f));

    // Layer 1 on UNNORMALIZED diffs (overlaps the MUFU rsqrt).
    u64 uA0, uA1, uA2, uA3, uA4, uB0, uB1, uB2, uB3, uB4;
    u64 B0, B1, B2, B3, B4;
    u64 wa, wb, wc;
#define L1ROW(UA, UB, BB, J)                                                \
    ldsw2(swb + (J) * 32u, wa, wb);                                         \
    ldsw2(swb + (J) * 32u + 16u, wc, BB);                                   \
    UA = dfma(dzA, wc, dfma(dyA, wb, dmul(dxA, wa)));                       \
    UB = dfma(dzB, wc, dfma(dyB, wb, dmul(dxB, wa)));
    L1ROW(uA0, uB0, B0, 0) L1ROW(uA1, uB1, B1, 1) L1ROW(uA2, uB2, B2, 2)
    L1ROW(uA3, uB3, B3, 3) L1ROW(uA4, uB4, B4, 4)
#undef L1ROW

    u64 invA = pk2(iA0, iA1);
    u64 invB = pk2(iB0, iB1);

    u64 hA0 = drelu2(dfma(uA0, invA, B0)), hB0 = drelu2(dfma(uB0, invB, B0));
    u64 hA1 = drelu2(dfma(uA1, invA, B1)), hB1 = drelu2(dfma(uB1, invB, B1));
    u64 hA2 = drelu2(dfma(uA2, invA, B2)), hB2 = drelu2(dfma(uB2, invB, B2));
    u64 hA3 = drelu2(dfma(uA3, invA, B3)), hB3 = drelu2(dfma(uB3, invB, B3));
    u64 hA4 = drelu2(dfma(uA4, invA, B4)), hB4 = drelu2(dfma(uB4, invB, B4));

    // Layer 2 (weights pre-scaled by 0.5): 3 paired LDS per row
    u64 wd, we, bj;
    u64 gA0, gA1, gA2, gA3, gA4, gB0, gB1, gB2, gB3, gB4;
#define L2ROW(GA, GB, J)                                                    \
    ldsw2(swb + 160u + (J) * 48u, wa, wb);                                  \
    ldsw2(swb + 176u + (J) * 48u, wc, wd);                                  \
    ldsw2(swb + 192u + (J) * 48u, we, bj);                                  \
    GA = dfma(hA0, wa, bj); GA = dfma(hA1, wb, GA); GA = dfma(hA2, wc, GA); \
    GA = dfma(hA3, wd, GA); GA = dfma(hA4, we, GA); GA = drelu2(GA);        \
    GB = dfma(hB0, wa, bj); GB = dfma(hB1, wb, GB); GB = dfma(hB2, wc, GB); \
    GB = dfma(hB3, wd, GB); GB = dfma(hB4, we, GB); GB = drelu2(GB);
    L2ROW(gA0, gB0, 0) L2ROW(gA1, gB1, 1) L2ROW(gA2, gB2, 2)
    L2ROW(gA3, gB3, 3) L2ROW(gA4, gB4, 4)
#undef L2ROW

    // Layer 3 (pre-scaled by 0.5): 3 paired LDS
    ldsw2(swb + 400u, wa, wb);
    ldsw2(swb + 416u, wc, wd);
    ldsw2(swb + 432u, we, bj);
    u64 wgA = dfma(gA0, wa, bj);
    wgA = dfma(gA1, wb, wgA); wgA = dfma(gA2, wc, wgA);
    wgA = dfma(gA3, wd, wgA); wgA = dfma(gA4, we, wgA);
    u64 wgB = dfma(gB0, wa, bj);
    wgB = dfma(gB1, wb, wgB); wgB = dfma(gB2, wc, wgB);
    wgB = dfma(gB3, wd, wgB); wgB = dfma(gB4, we, wgB);

    // vel contribution: d * (inv * w)
    u64 wiA = dmul(wgA, invA);
    u64 wiB = dmul(wgB, invB);
    u64 vx = dmul(dxA, wiA), vy = dmul(dyA, wiA), vz = dmul(dzA, wiA);
    vx = dfma(dxB, wiB, vx); vy = dfma(dyB, wiB, vy); vz = dfma(dzB, wiB, vz);

    // collapse packed halves, then reduce across the 8-lane cluster
    float x0, x1, y0, y1, z0, z1;
    upk(vx, x0, x1); upk(vy, y0, y1); upk(vz, z0, z1);
    float fx = x0 + x1, fy = y0 + y1, fz = z0 + z1;
    fx += __shfl_xor_sync(0xFFFFFFFFu, fx, 1);
    fy += __shfl_xor_sync(0xFFFFFFFFu, fy, 1);
    fz += __shfl_xor_sync(0xFFFFFFFFu, fz, 1);
    fx += __shfl_xor_sync(0xFFFFFFFFu, fx, 2);
    fy += __shfl_xor_sync(0xFFFFFFFFu, fy, 2);
    fz += __shfl_xor_sync(0xFFFFFFFFu, fz, 2);
    fx += __shfl_xor_sync(0xFFFFFFFFu, fx, 4);
    fy += __shfl_xor_sync(0xFFFFFFFFu, fy, 4);
    fz += __shfl_xor_sync(0xFFFFFFFFu, fz, 4);

    if (j == 0 && n < N) {
        float d2 = fmaf(fx, fx, fmaf(fy, fy, fz * fz));
        d2 = fmaxf(d2, 1e-24f);
        float r = rsqrtf(d2);
        r = r * fmaf(-0.5f * d2 * r, r, 1.5f);  // one Newton step
        out[3 * n + 0] = fx * r;
        out[3 * n + 1] = fy * r;
        out[3 * n + 2] = fz * r;
    }
}

extern "C" void kernel_launch(void* const* d_in, const int* in_sizes, int n_in,
                              void* d_out, int out_size)
{
    const float* pos = (const float*)d_in[0];
    const float* nbr = (const float*)d_in[1];
    const float* W1  = (const float*)d_in[2];
    const float* b1  = (const float*)d_in[3];
    const float* W2  = (const float*)d_in[4];
    const float* b2  = (const float*)d_in[5];
    const float* W3  = (const float*)d_in[6];
    const float* b3  = (const float*)d_in[7];
    float* out = (float*)d_out;

    // single launch: one warp per 4 points, 8 lanes per point
    int N = in_sizes[0] / 3;                 // positions is [N,3]
    long long warps = (N + 3) / 4;           // 4 points per warp
    int threads = 128;
    long long blocks = (warps * 32 + threads - 1) / threads;
    velvec_kernel<<<(int)blocks, threads>>>(pos, nbr, W1, b1, W2, b2, W3, b3,
                                            out, N);
}

// round 16
// speedup vs baseline: 1.0916x; 1.0916x over previous
#include <cuda_runtime.h>
#include <cstdint>

typedef unsigned long long u64;

// Packed (v,v) pre-scaled weights in the constant bank as 16B pairs -> LDC.128.
//  [2j] = (W1[j,0], W1[j,1])   [2j+1] = (W1[j,2], b1[j])          j=0..4
//  [10+3j] = (.5W2[j,0], .5W2[j,1]) [11+3j] = (.5W2[j,2], .5W2[j,3])
//  [12+3j] = (.5W2[j,4], b2[j])                                    j=0..4
//  [25] = (.5W3[0], .5W3[1])  [26] = (.5W3[2], .5W3[3])  [27] = (.5W3[4], b3)
__constant__ __align__(16) ulonglong2 c2[28];
__device__ __align__(16) u64 g_pack[56];

__global__ void pack_weights_kernel(const float* __restrict__ W1, const float* __restrict__ b1,
                                    const float* __restrict__ W2, const float* __restrict__ b2,
                                    const float* __restrict__ W3, const float* __restrict__ b3)
{
    int i = threadIdx.x;
    if (i >= 56) return;
    float v = 0.0f;
    if (i < 20) {
        int j = i >> 2, r = i & 3;
        v = (r < 3) ? W1[3 * j + r] : b1[j];
    } else if (i < 50) {
        int t = i - 20, j = t / 6, r = t - 6 * j;
        v = (r < 5) ? 0.5f * W2[5 * j + r] : b2[j];
    } else if (i < 55) {
        v = 0.5f * W3[i - 50];
    } else {
        v = b3[0];
    }
    unsigned int u = __float_as_uint(v);
    g_pack[i] = ((u64)u << 32) | (u64)u;
}

// ---------- packed f32x2 helpers ----------
__device__ __forceinline__ u64 pk2(float lo, float hi) {
    u64 r;
    asm("mov.b64 %0, {%1, %2};" : "=l"(r)
        : "r"(__float_as_uint(lo)), "r"(__float_as_uint(hi)));
    return r;
}
__device__ __forceinline__ void upk(u64 a, float& lo, float& hi) {
    unsigned int l_, h_;
    asm("mov.b64 {%0, %1}, %2;" : "=r"(l_), "=r"(h_) : "l"(a));
    lo = __uint_as_float(l_);
    hi = __uint_as_float(h_);
}
__device__ __forceinline__ u64 dfma(u64 a, u64 b, u64 c) {
    u64 d;
    asm("fma.rn.f32x2 %0, %1, %2, %3;" : "=l"(d) : "l"(a), "l"(b), "l"(c));
    return d;
}
__device__ __forceinline__ u64 dmul(u64 a, u64 b) {
    u64 d;
    asm("mul.rn.f32x2 %0, %1, %2;" : "=l"(d) : "l"(a), "l"(b));
    return d;
}
__device__ __forceinline__ u64 dadd(u64 a, u64 b) {
    u64 d;
    asm("add.rn.f32x2 %0, %1, %2;" : "=l"(d) : "l"(a), "l"(b));
    return d;
}
// 2*relu(x) per half, exact: x + |x| (2x folded into pre-halved W2/W3)
__device__ __forceinline__ u64 drelu2(u64 a) {
    return dadd(a, a & 0x7FFFFFFF7FFFFFFFULL);
}

// One warp = 8 points (two groups of 4); 8 lanes per point; each lane owns a
// contiguous 48B slice (4 neighbors = 2 packed pairs) in EACH group -> 4
// pairs per thread. Every constant LDC.128 is shared by all 4 pairs.
__global__ void __launch_bounds__(128)
velvec_kernel(const float* __restrict__ pos, const float* __restrict__ nbr,
              float* __restrict__ out, int N)
{
    int gw = (blockIdx.x * blockDim.x + threadIdx.x) >> 5;  // global warp id
    int l = threadIdx.x & 31;
    int p = l >> 3;            // point within group
    int j = l & 7;             // 48B slice within the point's 384B row
    int n0 = gw * 8 + p;       // group-0 point
    int n1 = n0 + 4;           // group-1 point
    int nc0 = (n0 < N) ? n0 : (N - 1);
    int nc1 = (n1 < N) ? n1 : (N - 1);

    // ---- loads: 2 x 3 LDG.128 (48B contiguous per point) ----
    const float4* bp0 = reinterpret_cast<const float4*>(
        (const char*)nbr + (size_t)nc0 * 384 + (size_t)j * 48);
    const float4* bp1 = reinterpret_cast<const float4*>(
        (const char*)nbr + (size_t)nc1 * 384 + (size_t)j * 48);
    float4 q0 = __ldg(bp0 + 0), q1 = __ldg(bp0 + 1), q2 = __ldg(bp0 + 2);
    float4 r0 = __ldg(bp1 + 0), r1 = __ldg(bp1 + 1), r2 = __ldg(bp1 + 2);

    float px0 = __ldg(pos + 3 * nc0 + 0);
    float py0 = __ldg(pos + 3 * nc0 + 1);
    float pz0 = __ldg(pos + 3 * nc0 + 2);
    float px1 = __ldg(pos + 3 * nc1 + 0);
    float py1 = __ldg(pos + 3 * nc1 + 1);
    float pz1 = __ldg(pos + 3 * nc1 + 2);
    u64 npx0 = pk2(-px0, -px0), npy0 = pk2(-py0, -py0), npz0 = pk2(-pz0, -pz0);
    u64 npx1 = pk2(-px1, -px1), npy1 = pk2(-py1, -py1), npz1 = pk2(-pz1, -pz1);

    // pairs A,B from group 0; C,D from group 1
    u64 dxA = dadd(pk2(q0.x, q0.w), npx0), dyA = dadd(pk2(q0.y, q1.x), npy0),
        dzA = dadd(pk2(q0.z, q1.y), npz0);
    u64 dxB = dadd(pk2(q1.z, q2.y), npx0), dyB = dadd(pk2(q1.w, q2.z), npy0),
        dzB = dadd(pk2(q2.x, q2.w), npz0);
    u64 dxC = dadd(pk2(r0.x, r0.w), npx1), dyC = dadd(pk2(r0.y, r1.x), npy1),
        dzC = dadd(pk2(r0.z, r1.y), npz1);
    u64 dxD = dadd(pk2(r1.z, r2.y), npx1), dyD = dadd(pk2(r1.w, r2.z), npy1),
        dzD = dadd(pk2(r2.x, r2.w), npz1);

    u64 d2A = dfma(dxA, dxA, dfma(dyA, dyA, dmul(dzA, dzA)));
    u64 d2B = dfma(dxB, dxB, dfma(dyB, dyB, dmul(dzB, dzB)));
    u64 d2C = dfma(dxC, dxC, dfma(dyC, dyC, dmul(dzC, dzC)));
    u64 d2D = dfma(dxD, dxD, dfma(dyD, dyD, dmul(dzD, dzD)));
    float sA0, sA1, sB0, sB1, sC0, sC1, sD0, sD1;
    upk(d2A, sA0, sA1); upk(d2B, sB0, sB1);
    upk(d2C, sC0, sC1); upk(d2D, sD0, sD1);
    // matches v/max(||v||,1e-12)
    float iA0 = rsqrtf(fmaxf(sA0, 1e-24f)), iA1 = rsqrtf(fmaxf(sA1, 1e-24f));
    float iB0 = rsqrtf(fmaxf(sB0, 1e-24f)), iB1 = rsqrtf(fmaxf(sB1, 1e-24f));
    float iC0 = rsqrtf(fmaxf(sC0, 1e-24f)), iC1 = rsqrtf(fmaxf(sC1, 1e-24f));
    float iD0 = rsqrtf(fmaxf(sD0, 1e-24f)), iD1 = rsqrtf(fmaxf(sD1, 1e-24f));

    // Layer 1 on UNNORMALIZED diffs (overlaps the 8 MUFU rsqrts).
    u64 uA0, uA1, uA2, uA3, uA4, uB0, uB1, uB2, uB3, uB4;
    u64 uC0, uC1, uC2, uC3, uC4, uD0, uD1, uD2, uD3, uD4;
    u64 B0, B1, B2, B3, B4;
#define L1ROW(UA, UB, UC, UD, BB, J)                                        \
    {                                                                       \
        ulonglong2 t0 = c2[2 * (J)];                                        \
        ulonglong2 t1 = c2[2 * (J) + 1];                                    \
        UA = dfma(dzA, t1.x, dfma(dyA, t0.y, dmul(dxA, t0.x)));             \
        UB = dfma(dzB, t1.x, dfma(dyB, t0.y, dmul(dxB, t0.x)));             \
        UC = dfma(dzC, t1.x, dfma(dyC, t0.y, dmul(dxC, t0.x)));             \
        UD = dfma(dzD, t1.x, dfma(dyD, t0.y, dmul(dxD, t0.x)));             \
        BB = t1.y;                                                          \
    }
    L1ROW(uA0, uB0, uC0, uD0, B0, 0) L1ROW(uA1, uB1, uC1, uD1, B1, 1)
    L1ROW(uA2, uB2, uC2, uD2, B2, 2) L1ROW(uA3, uB3, uC3, uD3, B3, 3)
    L1ROW(uA4, uB4, uC4, uD4, B4, 4)
#undef L1ROW

    u64 invA = pk2(iA0, iA1), invB = pk2(iB0, iB1);
    u64 invC = pk2(iC0, iC1), invD = pk2(iD0, iD1);

    u64 hA0 = drelu2(dfma(uA0, invA, B0)), hB0 = drelu2(dfma(uB0, invB, B0));
    u64 hC0 = drelu2(dfma(uC0, invC, B0)), hD0 = drelu2(dfma(uD0, invD, B0));
    u64 hA1 = drelu2(dfma(uA1, invA, B1)), hB1 = drelu2(dfma(uB1, invB, B1));
    u64 hC1 = drelu2(dfma(uC1, invC, B1)), hD1 = drelu2(dfma(uD1, invD, B1));
    u64 hA2 = drelu2(dfma(uA2, invA, B2)), hB2 = drelu2(dfma(uB2, invB, B2));
    u64 hC2 = drelu2(dfma(uC2, invC, B2)), hD2 = drelu2(dfma(uD2, invD, B2));
    u64 hA3 = drelu2(dfma(uA3, invA, B3)), hB3 = drelu2(dfma(uB3, invB, B3));
    u64 hC3 = drelu2(dfma(uC3, invC, B3)), hD3 = drelu2(dfma(uD3, invD, B3));
    u64 hA4 = drelu2(dfma(uA4, invA, B4)), hB4 = drelu2(dfma(uB4, invB, B4));
    u64 hC4 = drelu2(dfma(uC4, invC, B4)), hD4 = drelu2(dfma(uD4, invD, B4));

    // Layer 2 (weights pre-scaled by 0.5): 3 LDC.128 per row, used by 4 pairs
    u64 gA0, gA1, gA2, gA3, gA4, gB0, gB1, gB2, gB3, gB4;
    u64 gC0, gC1, gC2, gC3, gC4, gD0, gD1, gD2, gD3, gD4;
#define L2ROW(GA, GB, GC, GD, J)                                            \
    {                                                                       \
        ulonglong2 p0 = c2[10 + 3 * (J)];                                   \
        ulonglong2 p1 = c2[11 + 3 * (J)];                                   \
        ulonglong2 p2 = c2[12 + 3 * (J)];                                   \
        GA = dfma(hA0, p0.x, p2.y); GA = dfma(hA1, p0.y, GA);               \
        GA = dfma(hA2, p1.x, GA);   GA = dfma(hA3, p1.y, GA);               \
        GA = dfma(hA4, p2.x, GA);   GA = drelu2(GA);                        \
        GB = dfma(hB0, p0.x, p2.y); GB = dfma(hB1, p0.y, GB);               \
        GB = dfma(hB2, p1.x, GB);   GB = dfma(hB3, p1.y, GB);               \
        GB = dfma(hB4, p2.x, GB);   GB = drelu2(GB);                        \
        GC = dfma(hC0, p0.x, p2.y); GC = dfma(hC1, p0.y, GC);               \
        GC = dfma(hC2, p1.x, GC);   GC = dfma(hC3, p1.y, GC);               \
        GC = dfma(hC4, p2.x, GC);   GC = drelu2(GC);                        \
        GD = dfma(hD0, p0.x, p2.y); GD = dfma(hD1, p0.y, GD);               \
        GD = dfma(hD2, p1.x, GD);   GD = dfma(hD3, p1.y, GD);               \
        GD = dfma(hD4, p2.x, GD);   GD = drelu2(GD);                        \
    }
    L2ROW(gA0, gB0, gC0, gD0, 0) L2ROW(gA1, gB1, gC1, gD1, 1)
    L2ROW(gA2, gB2, gC2, gD2, 2) L2ROW(gA3, gB3, gC3, gD3, 3)
    L2ROW(gA4, gB4, gC4, gD4, 4)
#undef L2ROW

    // Layer 3 (pre-scaled by 0.5): 3 LDC.128 shared by 4 pairs
    ulonglong2 w0 = c2[25], w1p = c2[26], w2p = c2[27];
    u64 wgA = dfma(gA0, w0.x, w2p.y);
    wgA = dfma(gA1, w0.y, wgA); wgA = dfma(gA2, w1p.x, wgA);
    wgA = dfma(gA3, w1p.y, wgA); wgA = dfma(gA4, w2p.x, wgA);
    u64 wgB = dfma(gB0, w0.x, w2p.y);
    wgB = dfma(gB1, w0.y, wgB); wgB = dfma(gB2, w1p.x, wgB);
    wgB = dfma(gB3, w1p.y, wgB); wgB = dfma(gB4, w2p.x, wgB);
    u64 wgC = dfma(gC0, w0.x, w2p.y);
    wgC = dfma(gC1, w0.y, wgC); wgC = dfma(gC2, w1p.x, wgC);
    wgC = dfma(gC3, w1p.y, wgC); wgC = dfma(gC4, w2p.x, wgC);
    u64 wgD = dfma(gD0, w0.x, w2p.y);
    wgD = dfma(gD1, w0.y, wgD); wgD = dfma(gD2, w1p.x, wgD);
    wgD = dfma(gD3, w1p.y, wgD); wgD = dfma(gD4, w2p.x, wgD);

    // vel contribution: d * (inv * w), per group
    u64 wiA = dmul(wgA, invA), wiB = dmul(wgB, invB);
    u64 wiC = dmul(wgC, invC), wiD = dmul(wgD, invD);
    u64 vx0 = dmul(dxA, wiA), vy0 = dmul(dyA, wiA), vz0 = dmul(dzA, wiA);
    vx0 = dfma(dxB, wiB, vx0); vy0 = dfma(dyB, wiB, vy0); vz0 = dfma(dzB, wiB, vz0);
    u64 vx1 = dmul(dxC, wiC), vy1 = dmul(dyC, wiC), vz1 = dmul(dzC, wiC);
    vx1 = dfma(dxD, wiD, vx1); vy1 = dfma(dyD, wiD, vy1); vz1 = dfma(dzD, wiD, vz1);

    // collapse packed halves; reduce both groups across the 8-lane cluster
    float a0, a1;
    upk(vx0, a0, a1); float fx0 = a0 + a1;
    upk(vy0, a0, a1); float fy0 = a0 + a1;
    upk(vz0, a0, a1); float fz0 = a0 + a1;
    upk(vx1, a0, a1); float fx1 = a0 + a1;
    upk(vy1, a0, a1); float fy1 = a0 + a1;
    upk(vz1, a0, a1); float fz1 = a0 + a1;
#pragma unroll
    for (int d = 1; d < 8; d <<= 1) {
        fx0 += __shfl_xor_sync(0xFFFFFFFFu, fx0, d);
        fy0 += __shfl_xor_sync(0xFFFFFFFFu, fy0, d);
        fz0 += __shfl_xor_sync(0xFFFFFFFFu, fz0, d);
        fx1 += __shfl_xor_sync(0xFFFFFFFFu, fx1, d);
        fy1 += __shfl_xor_sync(0xFFFFFFFFu, fy1, d);
        fz1 += __shfl_xor_sync(0xFFFFFFFFu, fz1, d);
    }

    if (j == 0) {
        if (n0 < N) {
            float d2 = fmaf(fx0, fx0, fmaf(fy0, fy0, fz0 * fz0));
            d2 = fmaxf(d2, 1e-24f);
            float r = rsqrtf(d2);
            r = r * fmaf(-0.5f * d2 * r, r, 1.5f);  // one Newton step
            out[3 * n0 + 0] = fx0 * r;
            out[3 * n0 + 1] = fy0 * r;
            out[3 * n0 + 2] = fz0 * r;
        }
        if (n1 < N) {
            float d2 = fmaf(fx1, fx1, fmaf(fy1, fy1, fz1 * fz1));
            d2 = fmaxf(d2, 1e-24f);
            float r = rsqrtf(d2);
            r = r * fmaf(-0.5f * d2 * r, r, 1.5f);
            out[3 * n1 + 0] = fx1 * r;
            out[3 * n1 + 1] = fy1 * r;
            out[3 * n1 + 2] = fz1 * r;
        }
    }
}

extern "C" void kernel_launch(void* const* d_in, const int* in_sizes, int n_in,
                              void* d_out, int out_size)
{
    const float* pos = (const float*)d_in[0];
    const float* nbr = (const float*)d_in[1];
    const float* W1  = (const float*)d_in[2];
    const float* b1  = (const float*)d_in[3];
    const float* W2  = (const float*)d_in[4];
    const float* b2  = (const float*)d_in[5];
    const float* W3  = (const float*)d_in[6];
    const float* b3  = (const float*)d_in[7];
    float* out = (float*)d_out;

    // 1) pack + pre-scale weights (paired order) into a __device__ buffer
    pack_weights_kernel<<<1, 64>>>(W1, b1, W2, b2, W3, b3);

    // 2) D2D async copy into the constant bank (graph-capturable memcpy node)
    void* src = nullptr;
    cudaGetSymbolAddress(&src, g_pack);
    cudaMemcpyToSymbolAsync(c2, src, 56 * sizeof(u64), 0,
                            cudaMemcpyDeviceToDevice, 0);

    // 3) main kernel: one warp per 8 points (two groups of 4)
    int N = in_sizes[0] / 3;                 // positions is [N,3]
    long long warps = (N + 7) / 8;           // 8 points per warp
    int threads = 128;
    long long blocks = (warps * 32 + threads - 1) / threads;
    velvec_kernel<<<(int)blocks, threads>>>(pos, nbr, out, N);
}